// round 14
// baseline (speedup 1.0000x reference)
#include <cuda_runtime.h>
#include <cuda_fp16.h>
#include <cstdint>
#include <cstddef>

#define T_TOK 1024
#define HID   2048
#define IDIM  1024
#define NEXP  32
#define NGRP  8
#define EPG   4
#define TOPG  4
#define TOPK  8
#define NE    33      // 32 routed + 1 shared
#define CAP   1024
#define RSCALE 2.5f

// GEMM tiling: CTA 128x128, 4 warps of 64x64, BK=32, double buffer, cp.async A
#define BK    32
#define STR   40                 // padded fp16 row stride (80B, conflict-free ldmatrix)
#define TILEB (128 * STR * 2)    // 10240 bytes per 128xBK fp16 tile
#define BUFB  (2 * TILEB)        // A + B = 20480
#define SMEMB (2 * BUFB)         // double buffer = 40960

// ---------------- static scratch (no allocations allowed) ----------------
__device__ float  g_combine[T_TOK * NEXP];
__device__ int    g_count[NE];
__device__ int    g_token[NE * CAP];
__device__ float  g_wt[NE * CAP];
__device__ int    g_rowid[NEXP * T_TOK];                    // [e][t] -> row or -1
__device__ __half g_xh[(size_t)T_TOK * HID];                // x in fp16
__device__ __half g_act[(size_t)NE * CAP * IDIM];           // silu(g)*u rows (fp16)
__device__ float  g_down[(size_t)NE * CAP * HID];           // weighted down-proj rows

__device__ __forceinline__ float silu_f(float v) {
    return v / (1.0f + expf(-v));
}

__device__ __forceinline__ uint32_t smem_u32(const void* p) {
    uint32_t a;
    asm("{ .reg .u64 t; cvta.to.shared.u64 t, %1; cvt.u32.u64 %0, t; }"
        : "=r"(a) : "l"(p));
    return a;
}

__device__ __forceinline__ void ldm4(uint32_t* r, uint32_t addr) {
    asm volatile("ldmatrix.sync.aligned.m8n8.x4.shared.b16 {%0,%1,%2,%3}, [%4];"
        : "=r"(r[0]), "=r"(r[1]), "=r"(r[2]), "=r"(r[3]) : "r"(addr));
}
__device__ __forceinline__ void mma16816h(float* c, const uint32_t* a, const uint32_t* b) {
    asm volatile("mma.sync.aligned.m16n8k16.row.col.f32.f16.f16.f32 "
        "{%0,%1,%2,%3}, {%4,%5,%6,%7}, {%8,%9}, {%0,%1,%2,%3};"
        : "+f"(c[0]), "+f"(c[1]), "+f"(c[2]), "+f"(c[3])
        : "r"(a[0]), "r"(a[1]), "r"(a[2]), "r"(a[3]), "r"(b[0]), "r"(b[1]));
}

// fp32x4 -> fp16, store 8B
__device__ __forceinline__ void store_h(uint32_t a, float4 v) {
    __half h0 = __float2half_rn(v.x), h1 = __float2half_rn(v.y);
    __half h2 = __float2half_rn(v.z), h3 = __float2half_rn(v.w);
    unsigned long long H =
        (unsigned long long)__half_as_ushort(h0) |
        ((unsigned long long)__half_as_ushort(h1) << 16) |
        ((unsigned long long)__half_as_ushort(h2) << 32) |
        ((unsigned long long)__half_as_ushort(h3) << 48);
    asm volatile("st.shared.b64 [%0], %1;" :: "r"(a), "l"(H) : "memory");
}

#define CP_ASYNC16(dst, src) \
    asm volatile("cp.async.ca.shared.global [%0], [%1], 16;" :: "r"(dst), "l"(src) : "memory")
#define CP_COMMIT() asm volatile("cp.async.commit_group;" ::: "memory")
#define CP_WAIT0()  asm volatile("cp.async.wait_group 0;" ::: "memory")

// ---------------- 0) x -> fp16 prepass ----------------
__global__ void xcvt_kernel(const float* __restrict__ x) {
    size_t i = ((size_t)blockIdx.x * blockDim.x + threadIdx.x) * 4;
    float4 v = *(const float4*)(x + i);
    __half2* o = (__half2*)(g_xh + i);
    o[0] = __floats2half2_rn(v.x, v.y);
    o[1] = __floats2half2_rn(v.z, v.w);
}

// ---------------- 1) router ----------------
__global__ void router_kernel(const float* __restrict__ x,
                              const float* __restrict__ gw,
                              const float* __restrict__ bias) {
    __shared__ float sx[HID];
    __shared__ float slog[NEXP];
    int t = blockIdx.x;
    const float* xr = x + (size_t)t * HID;
    for (int k = threadIdx.x; k < HID; k += blockDim.x) sx[k] = xr[k];
    __syncthreads();
    int warp = threadIdx.x >> 5, lane = threadIdx.x & 31;
    for (int e = warp; e < NEXP; e += 8) {
        const float* w = gw + (size_t)e * HID;
        float acc = 0.f;
        for (int k = lane; k < HID; k += 32) acc = fmaf(sx[k], w[k], acc);
        #pragma unroll
        for (int o = 16; o; o >>= 1) acc += __shfl_down_sync(0xffffffffu, acc, o);
        if (lane == 0) slog[e] = acc;
    }
    __syncthreads();
    if (threadIdx.x == 0) {
        float s[NEXP], sr[NEXP];
        #pragma unroll
        for (int e = 0; e < NEXP; e++) {
            float sc = 1.f / (1.f + expf(-slog[e]));
            s[e] = sc;
            sr[e] = sc + bias[e];
        }
        float gs[NGRP];
        #pragma unroll
        for (int g = 0; g < NGRP; g++) {
            float m1 = -1e30f, m2 = -1e30f;
            #pragma unroll
            for (int j = 0; j < EPG; j++) {
                float v = sr[g * EPG + j];
                if (v > m1) { m2 = m1; m1 = v; }
                else if (v > m2) { m2 = v; }
            }
            gs[g] = m1 + m2;
        }
        bool gsel[NGRP];
        #pragma unroll
        for (int g = 0; g < NGRP; g++) gsel[g] = false;
        for (int it = 0; it < TOPG; it++) {
            float best = -1e30f; int bi = 0;
            for (int g = 0; g < NGRP; g++)
                if (!gsel[g] && gs[g] > best) { best = gs[g]; bi = g; }
            gsel[bi] = true;
        }
        bool taken[NEXP];
        #pragma unroll
        for (int e = 0; e < NEXP; e++) taken[e] = false;
        int ids[TOPK];
        for (int it = 0; it < TOPK; it++) {
            float best = -1e30f; int bi = 0;
            for (int e = 0; e < NEXP; e++)
                if (gsel[e >> 2] && !taken[e] && sr[e] > best) { best = sr[e]; bi = e; }
            taken[bi] = true;
            ids[it] = bi;
        }
        float sum = 0.f;
        for (int k = 0; k < TOPK; k++) sum += s[ids[k]];
        float inv = RSCALE / (sum + 1e-20f);
        float out[NEXP];
        #pragma unroll
        for (int e = 0; e < NEXP; e++) out[e] = 0.f;
        for (int k = 0; k < TOPK; k++) out[ids[k]] = s[ids[k]] * inv;
        #pragma unroll
        for (int e = 0; e < NEXP; e++) g_combine[t * NEXP + e] = out[e];
    }
}

// ---------------- 2) compact per-expert token lists ----------------
__global__ void build_lists_kernel() {
    int e = blockIdx.x;
    int t = threadIdx.x;
    __shared__ int sc[T_TOK];
    float w;
    int flag;
    if (e < NEXP) {
        w = g_combine[t * NEXP + e];
        flag = (w > 0.f) ? 1 : 0;
    } else {
        w = 1.0f;
        flag = 1;
    }
    sc[t] = flag;
    __syncthreads();
    for (int off = 1; off < T_TOK; off <<= 1) {
        int v = (t >= off) ? sc[t - off] : 0;
        __syncthreads();
        sc[t] += v;
        __syncthreads();
    }
    int pos = sc[t] - flag;
    if (flag) {
        g_token[e * CAP + pos] = t;
        g_wt[e * CAP + pos] = w;
    }
    if (e < NEXP) g_rowid[e * T_TOK + t] = flag ? (e * CAP + pos) : -1;
    if (t == T_TOK - 1) g_count[e] = sc[T_TOK - 1];
}

// ---------------- 3) gate_up GEMM: fp16 mma, 64x64 warp tiles --------------
// CTA: 128 rows x 128 D-cols interleaved (even=gate j, odd=up j).
// 128 threads = 4 warps in 2x2 grid of 64x64 tiles; 2 CTAs/SM.
__global__ void __launch_bounds__(128, 2)
gateup_mma(const float* __restrict__ wgu,
           const float* __restrict__ sgu) {
    int e = blockIdx.z;
    int cnt = g_count[e];
    int m0 = blockIdx.x * 128;
    if (m0 >= cnt) return;
    int n0 = blockIdx.y * 64;
    const float* W = (e < NEXP) ? (wgu + (size_t)e * (2 * IDIM) * HID) : sgu;

    extern __shared__ char smem[];
    uint32_t sb = smem_u32(smem);
    int tid = threadIdx.x;
    int lane = tid & 31, wid = tid >> 5;

    // A cp.async: 512 x 16B ops (128 rows x 4 segs); thread does 4 ops
    int ar = tid >> 2, as = tid & 3;
    const __half* asrc[4];
    uint32_t adst[4];
    #pragma unroll
    for (int i = 0; i < 4; i++) {
        int row = ar + 32 * i;
        int mr = m0 + row; if (mr > cnt - 1) mr = cnt - 1;
        asrc[i] = g_xh + (size_t)g_token[e * CAP + mr] * HID + as * 8;
        adst[i] = (uint32_t)(row * STR + as * 8) * 2;
    }

    // B loader: thread t owns row t (32 fp32 -> 32 fp16)
    int jcol = tid >> 1;
    int wrow = (tid & 1) ? (IDIM + n0 + jcol) : (n0 + jcol);
    const float* bptr = W + (size_t)wrow * HID;
    uint32_t bdst = TILEB + (uint32_t)(tid * STR) * 2;

    // warp grid 2x2: each warp 64 rows x 64 cols
    int wm0 = (wid >> 1) * 64, wn0 = (wid & 1) * 64;
    uint32_t a_r = (uint32_t)(wm0 + (lane & 15));
    uint32_t a_c8 = (uint32_t)((lane >> 4) * 8);
    uint32_t b_row = (uint32_t)((lane & 7) + ((lane >> 4) << 3));
    uint32_t b_k8 = (uint32_t)(((lane >> 3) & 1) * 8);

    float acc[4][8][4];
    #pragma unroll
    for (int mi = 0; mi < 4; mi++)
        #pragma unroll
        for (int ni = 0; ni < 8; ni++)
            #pragma unroll
            for (int q = 0; q < 4; q++) acc[mi][ni][q] = 0.f;

    float4 rb[8];
    // prologue: chunk 0
    #pragma unroll
    for (int i = 0; i < 4; i++) CP_ASYNC16(sb + adst[i], asrc[i]);
    CP_COMMIT();
    #pragma unroll
    for (int q = 0; q < 8; q++) rb[q] = *(const float4*)(bptr + q * 4);
    #pragma unroll
    for (int q = 0; q < 8; q++) store_h(sb + bdst + q * 8, rb[q]);
    CP_WAIT0();
    __syncthreads();

    const int NC = HID / BK;  // 64
    for (int c = 0; c < NC; c++) {
        if (c + 1 < NC) {
            uint32_t nb = sb + (uint32_t)((c + 1) & 1) * BUFB;
            #pragma unroll
            for (int i = 0; i < 4; i++)
                CP_ASYNC16(nb + adst[i], asrc[i] + (c + 1) * BK);
            CP_COMMIT();
            const float* bp = bptr + (c + 1) * BK;
            #pragma unroll
            for (int q = 0; q < 8; q++) rb[q] = *(const float4*)(bp + q * 4);
        }
        uint32_t cur = sb + (uint32_t)(c & 1) * BUFB;
        #pragma unroll
        for (int kh = 0; kh < 2; kh++) {
            uint32_t ah[4][4], bh[4][4];
            #pragma unroll
            for (int mi = 0; mi < 4; mi++) {
                uint32_t ad = cur + ((a_r + mi * 16) * STR + kh * 16 + a_c8) * 2;
                ldm4(ah[mi], ad);
            }
            #pragma unroll
            for (int nj = 0; nj < 4; nj++) {
                uint32_t bd = cur + TILEB +
                    ((wn0 + nj * 16 + b_row) * STR + kh * 16 + b_k8) * 2;
                ldm4(bh[nj], bd);
            }
            #pragma unroll
            for (int mi = 0; mi < 4; mi++)
                #pragma unroll
                for (int ni = 0; ni < 8; ni++) {
                    const uint32_t* bhp = &bh[ni >> 1][(ni & 1) * 2];
                    mma16816h(acc[mi][ni], ah[mi], bhp);
                }
        }
        if (c + 1 < NC) {
            uint32_t nb = sb + (uint32_t)((c + 1) & 1) * BUFB;
            #pragma unroll
            for (int q = 0; q < 8; q++) store_h(nb + bdst + q * 8, rb[q]);
        }
        CP_WAIT0();
        __syncthreads();
    }

    // epilogue: c0=gate, c1=up for col j; rows g and g+8 -> fp16 g_act
    int g = lane >> 2, tc = (lane & 3) * 2;
    #pragma unroll
    for (int mi = 0; mi < 4; mi++) {
        int r0 = m0 + wm0 + mi * 16 + g;
        int r1 = r0 + 8;
        #pragma unroll
        for (int ni = 0; ni < 8; ni++) {
            int col = n0 + ((wn0 + ni * 8 + tc) >> 1);
            if (r0 < cnt)
                g_act[((size_t)e * CAP + r0) * IDIM + col] =
                    __float2half_rn(silu_f(acc[mi][ni][0]) * acc[mi][ni][1]);
            if (r1 < cnt)
                g_act[((size_t)e * CAP + r1) * IDIM + col] =
                    __float2half_rn(silu_f(acc[mi][ni][2]) * acc[mi][ni][3]);
        }
    }
}

// ---------------- 4) down GEMM: fp16 mma, 64x64 warp tiles, weighted -------
__global__ void __launch_bounds__(128, 2)
down_mma(const float* __restrict__ wdn,
         const float* __restrict__ sdn) {
    int e = blockIdx.z;
    int cnt = g_count[e];
    int m0 = blockIdx.x * 128;
    if (m0 >= cnt) return;
    int n0 = blockIdx.y * 128;
    const float* W = (e < NEXP) ? (wdn + (size_t)e * HID * IDIM) : sdn;

    extern __shared__ char smem[];
    uint32_t sb = smem_u32(smem);
    int tid = threadIdx.x;
    int lane = tid & 31, wid = tid >> 5;

    int ar = tid >> 2, as = tid & 3;
    const __half* asrc[4];
    uint32_t adst[4];
    #pragma unroll
    for (int i = 0; i < 4; i++) {
        int row = ar + 32 * i;
        int mr = m0 + row; if (mr > cnt - 1) mr = cnt - 1;
        asrc[i] = g_act + ((size_t)e * CAP + mr) * IDIM + as * 8;
        adst[i] = (uint32_t)(row * STR + as * 8) * 2;
    }

    const float* bptr = W + (size_t)(n0 + tid) * IDIM;
    uint32_t bdst = TILEB + (uint32_t)(tid * STR) * 2;

    int wm0 = (wid >> 1) * 64, wn0 = (wid & 1) * 64;
    uint32_t a_r = (uint32_t)(wm0 + (lane & 15));
    uint32_t a_c8 = (uint32_t)((lane >> 4) * 8);
    uint32_t b_row = (uint32_t)((lane & 7) + ((lane >> 4) << 3));
    uint32_t b_k8 = (uint32_t)(((lane >> 3) & 1) * 8);

    float acc[4][8][4];
    #pragma unroll
    for (int mi = 0; mi < 4; mi++)
        #pragma unroll
        for (int ni = 0; ni < 8; ni++)
            #pragma unroll
            for (int q = 0; q < 4; q++) acc[mi][ni][q] = 0.f;

    float4 rb[8];
    #pragma unroll
    for (int i = 0; i < 4; i++) CP_ASYNC16(sb + adst[i], asrc[i]);
    CP_COMMIT();
    #pragma unroll
    for (int q = 0; q < 8; q++) rb[q] = *(const float4*)(bptr + q * 4);
    #pragma unroll
    for (int q = 0; q < 8; q++) store_h(sb + bdst + q * 8, rb[q]);
    CP_WAIT0();
    __syncthreads();

    const int NC = IDIM / BK;  // 32
    for (int c = 0; c < NC; c++) {
        if (c + 1 < NC) {
            uint32_t nb = sb + (uint32_t)((c + 1) & 1) * BUFB;
            #pragma unroll
            for (int i = 0; i < 4; i++)
                CP_ASYNC16(nb + adst[i], asrc[i] + (c + 1) * BK);
            CP_COMMIT();
            const float* bp = bptr + (c + 1) * BK;
            #pragma unroll
            for (int q = 0; q < 8; q++) rb[q] = *(const float4*)(bp + q * 4);
        }
        uint32_t cur = sb + (uint32_t)(c & 1) * BUFB;
        #pragma unroll
        for (int kh = 0; kh < 2; kh++) {
            uint32_t ah[4][4], bh[4][4];
            #pragma unroll
            for (int mi = 0; mi < 4; mi++) {
                uint32_t ad = cur + ((a_r + mi * 16) * STR + kh * 16 + a_c8) * 2;
                ldm4(ah[mi], ad);
            }
            #pragma unroll
            for (int nj = 0; nj < 4; nj++) {
                uint32_t bd = cur + TILEB +
                    ((wn0 + nj * 16 + b_row) * STR + kh * 16 + b_k8) * 2;
                ldm4(bh[nj], bd);
            }
            #pragma unroll
            for (int mi = 0; mi < 4; mi++)
                #pragma unroll
                for (int ni = 0; ni < 8; ni++) {
                    const uint32_t* bhp = &bh[ni >> 1][(ni & 1) * 2];
                    mma16816h(acc[mi][ni], ah[mi], bhp);
                }
        }
        if (c + 1 < NC) {
            uint32_t nb = sb + (uint32_t)((c + 1) & 1) * BUFB;
            #pragma unroll
            for (int q = 0; q < 8; q++) store_h(nb + bdst + q * 8, rb[q]);
        }
        CP_WAIT0();
        __syncthreads();
    }

    int g = lane >> 2, tc = (lane & 3) * 2;
    #pragma unroll
    for (int mi = 0; mi < 4; mi++) {
        int r0 = m0 + wm0 + mi * 16 + g;
        int r1 = r0 + 8;
        float w0 = (r0 < cnt) ? g_wt[e * CAP + r0] : 0.f;
        float w1 = (r1 < cnt) ? g_wt[e * CAP + r1] : 0.f;
        #pragma unroll
        for (int ni = 0; ni < 8; ni++) {
            int col = n0 + wn0 + ni * 8 + tc;
            if (r0 < cnt) {
                float2 v = make_float2(acc[mi][ni][0] * w0, acc[mi][ni][1] * w0);
                *(float2*)(g_down + ((size_t)e * CAP + r0) * HID + col) = v;
            }
            if (r1 < cnt) {
                float2 v = make_float2(acc[mi][ni][2] * w1, acc[mi][ni][3] * w1);
                *(float2*)(g_down + ((size_t)e * CAP + r1) * HID + col) = v;
            }
        }
    }
}

// ---------------- 5) deterministic per-token combine ----------------
__global__ void combine_kernel(float* __restrict__ y) {
    int t = blockIdx.x;
    __shared__ int rows[NEXP];
    if (threadIdx.x < NEXP) rows[threadIdx.x] = g_rowid[threadIdx.x * T_TOK + t];
    __syncthreads();
    int h0 = threadIdx.x * 8;
    const float* sh = g_down + ((size_t)NEXP * CAP + t) * HID + h0;
    float4 s0 = *(const float4*)sh;
    float4 s1 = *(const float4*)(sh + 4);
    for (int e = 0; e < NEXP; e++) {
        int r = rows[e];
        if (r >= 0) {
            const float* p = g_down + (size_t)r * HID + h0;
            float4 a = *(const float4*)p;
            float4 b = *(const float4*)(p + 4);
            s0.x += a.x; s0.y += a.y; s0.z += a.z; s0.w += a.w;
            s1.x += b.x; s1.y += b.y; s1.z += b.z; s1.w += b.w;
        }
    }
    float* out = y + (size_t)t * HID + h0;
    *(float4*)out = s0;
    *(float4*)(out + 4) = s1;
}

// ---------------- launcher ----------------
extern "C" void kernel_launch(void* const* d_in, const int* in_sizes, int n_in,
                              void* d_out, int out_size) {
    const float* x    = (const float*)d_in[0];
    const float* gw   = (const float*)d_in[1];
    const float* bias = (const float*)d_in[2];
    const float* wgu  = (const float*)d_in[3];
    const float* wdn  = (const float*)d_in[4];
    const float* sgu  = (const float*)d_in[5];
    const float* sdn  = (const float*)d_in[6];
    float* y = (float*)d_out;

    cudaFuncSetAttribute(gateup_mma, cudaFuncAttributeMaxDynamicSharedMemorySize, SMEMB);
    cudaFuncSetAttribute(down_mma, cudaFuncAttributeMaxDynamicSharedMemorySize, SMEMB);

    xcvt_kernel<<<(T_TOK * HID) / (256 * 4), 256>>>(x);
    router_kernel<<<T_TOK, 256>>>(x, gw, bias);
    build_lists_kernel<<<NE, T_TOK>>>();
    dim3 ga(CAP / 128, IDIM / 64, NE);
    gateup_mma<<<ga, 128, SMEMB>>>(wgu, sgu);
    dim3 gd(CAP / 128, HID / 128, NE);
    down_mma<<<gd, 128, SMEMB>>>(wdn, sdn);
    combine_kernel<<<T_TOK, 256>>>(y);
}

// round 15
// speedup vs baseline: 1.5427x; 1.5427x over previous
#include <cuda_runtime.h>
#include <cuda_fp16.h>
#include <cstdint>
#include <cstddef>

#define T_TOK 1024
#define HID   2048
#define IDIM  1024
#define NEXP  32
#define NGRP  8
#define EPG   4
#define TOPG  4
#define TOPK  8
#define NE    33      // 32 routed + 1 shared
#define CAP   1024
#define RSCALE 2.5f

// GEMM tiling: CTA 128x128, 8 warps of 64x32, BK=32, double buffer, cp.async A
#define BK    32
#define STR   40                 // padded fp16 row stride (80B, conflict-free ldmatrix)
#define TILEB (128 * STR * 2)    // 10240 bytes per 128xBK fp16 tile
#define BUFB  (2 * TILEB)        // A + B = 20480
#define SMEMB (2 * BUFB)         // double buffer = 40960

// ---------------- static scratch (no allocations allowed) ----------------
__device__ float  g_combine[T_TOK * NEXP];
__device__ int    g_count[NE];
__device__ int    g_token[NE * CAP];
__device__ float  g_wt[NE * CAP];
__device__ int    g_rowid[NEXP * T_TOK];                    // [e][t] -> row or -1
__device__ __half g_xh[(size_t)T_TOK * HID];                // x in fp16
__device__ __half g_act[(size_t)NE * CAP * IDIM];           // silu(g)*u rows (fp16)
__device__ float  g_down[(size_t)NE * CAP * HID];           // weighted down-proj rows

__device__ __forceinline__ float silu_f(float v) {
    return v / (1.0f + expf(-v));
}

__device__ __forceinline__ uint32_t smem_u32(const void* p) {
    uint32_t a;
    asm("{ .reg .u64 t; cvta.to.shared.u64 t, %1; cvt.u32.u64 %0, t; }"
        : "=r"(a) : "l"(p));
    return a;
}

__device__ __forceinline__ void ldm4(uint32_t* r, uint32_t addr) {
    asm volatile("ldmatrix.sync.aligned.m8n8.x4.shared.b16 {%0,%1,%2,%3}, [%4];"
        : "=r"(r[0]), "=r"(r[1]), "=r"(r[2]), "=r"(r[3]) : "r"(addr));
}
__device__ __forceinline__ void mma16816h(float* c, const uint32_t* a, const uint32_t* b) {
    asm volatile("mma.sync.aligned.m16n8k16.row.col.f32.f16.f16.f32 "
        "{%0,%1,%2,%3}, {%4,%5,%6,%7}, {%8,%9}, {%0,%1,%2,%3};"
        : "+f"(c[0]), "+f"(c[1]), "+f"(c[2]), "+f"(c[3])
        : "r"(a[0]), "r"(a[1]), "r"(a[2]), "r"(a[3]), "r"(b[0]), "r"(b[1]));
}

// fp32x4 -> fp16, store 8B
__device__ __forceinline__ void store_h(uint32_t a, float4 v) {
    __half h0 = __float2half_rn(v.x), h1 = __float2half_rn(v.y);
    __half h2 = __float2half_rn(v.z), h3 = __float2half_rn(v.w);
    unsigned long long H =
        (unsigned long long)__half_as_ushort(h0) |
        ((unsigned long long)__half_as_ushort(h1) << 16) |
        ((unsigned long long)__half_as_ushort(h2) << 32) |
        ((unsigned long long)__half_as_ushort(h3) << 48);
    asm volatile("st.shared.b64 [%0], %1;" :: "r"(a), "l"(H) : "memory");
}

#define CP_ASYNC16(dst, src) \
    asm volatile("cp.async.ca.shared.global [%0], [%1], 16;" :: "r"(dst), "l"(src) : "memory")
#define CP_COMMIT() asm volatile("cp.async.commit_group;" ::: "memory")
#define CP_WAIT0()  asm volatile("cp.async.wait_group 0;" ::: "memory")

// ---------------- 0) x -> fp16 prepass ----------------
__global__ void xcvt_kernel(const float* __restrict__ x) {
    size_t i = ((size_t)blockIdx.x * blockDim.x + threadIdx.x) * 4;
    float4 v = *(const float4*)(x + i);
    __half2* o = (__half2*)(g_xh + i);
    o[0] = __floats2half2_rn(v.x, v.y);
    o[1] = __floats2half2_rn(v.z, v.w);
}

// ---------------- 1) router ----------------
__global__ void router_kernel(const float* __restrict__ x,
                              const float* __restrict__ gw,
                              const float* __restrict__ bias) {
    __shared__ float sx[HID];
    __shared__ float slog[NEXP];
    int t = blockIdx.x;
    const float* xr = x + (size_t)t * HID;
    for (int k = threadIdx.x; k < HID; k += blockDim.x) sx[k] = xr[k];
    __syncthreads();
    int warp = threadIdx.x >> 5, lane = threadIdx.x & 31;
    for (int e = warp; e < NEXP; e += 8) {
        const float* w = gw + (size_t)e * HID;
        float acc = 0.f;
        for (int k = lane; k < HID; k += 32) acc = fmaf(sx[k], w[k], acc);
        #pragma unroll
        for (int o = 16; o; o >>= 1) acc += __shfl_down_sync(0xffffffffu, acc, o);
        if (lane == 0) slog[e] = acc;
    }
    __syncthreads();
    if (threadIdx.x == 0) {
        float s[NEXP], sr[NEXP];
        #pragma unroll
        for (int e = 0; e < NEXP; e++) {
            float sc = 1.f / (1.f + expf(-slog[e]));
            s[e] = sc;
            sr[e] = sc + bias[e];
        }
        float gs[NGRP];
        #pragma unroll
        for (int g = 0; g < NGRP; g++) {
            float m1 = -1e30f, m2 = -1e30f;
            #pragma unroll
            for (int j = 0; j < EPG; j++) {
                float v = sr[g * EPG + j];
                if (v > m1) { m2 = m1; m1 = v; }
                else if (v > m2) { m2 = v; }
            }
            gs[g] = m1 + m2;
        }
        bool gsel[NGRP];
        #pragma unroll
        for (int g = 0; g < NGRP; g++) gsel[g] = false;
        for (int it = 0; it < TOPG; it++) {
            float best = -1e30f; int bi = 0;
            for (int g = 0; g < NGRP; g++)
                if (!gsel[g] && gs[g] > best) { best = gs[g]; bi = g; }
            gsel[bi] = true;
        }
        bool taken[NEXP];
        #pragma unroll
        for (int e = 0; e < NEXP; e++) taken[e] = false;
        int ids[TOPK];
        for (int it = 0; it < TOPK; it++) {
            float best = -1e30f; int bi = 0;
            for (int e = 0; e < NEXP; e++)
                if (gsel[e >> 2] && !taken[e] && sr[e] > best) { best = sr[e]; bi = e; }
            taken[bi] = true;
            ids[it] = bi;
        }
        float sum = 0.f;
        for (int k = 0; k < TOPK; k++) sum += s[ids[k]];
        float inv = RSCALE / (sum + 1e-20f);
        float out[NEXP];
        #pragma unroll
        for (int e = 0; e < NEXP; e++) out[e] = 0.f;
        for (int k = 0; k < TOPK; k++) out[ids[k]] = s[ids[k]] * inv;
        #pragma unroll
        for (int e = 0; e < NEXP; e++) g_combine[t * NEXP + e] = out[e];
    }
}

// ---------------- 2) compact per-expert token lists ----------------
__global__ void build_lists_kernel() {
    int e = blockIdx.x;
    int t = threadIdx.x;
    __shared__ int sc[T_TOK];
    float w;
    int flag;
    if (e < NEXP) {
        w = g_combine[t * NEXP + e];
        flag = (w > 0.f) ? 1 : 0;
    } else {
        w = 1.0f;
        flag = 1;
    }
    sc[t] = flag;
    __syncthreads();
    for (int off = 1; off < T_TOK; off <<= 1) {
        int v = (t >= off) ? sc[t - off] : 0;
        __syncthreads();
        sc[t] += v;
        __syncthreads();
    }
    int pos = sc[t] - flag;
    if (flag) {
        g_token[e * CAP + pos] = t;
        g_wt[e * CAP + pos] = w;
    }
    if (e < NEXP) g_rowid[e * T_TOK + t] = flag ? (e * CAP + pos) : -1;
    if (t == T_TOK - 1) g_count[e] = sc[T_TOK - 1];
}

// ---------------- 3) gate_up GEMM: fp16 mma, coalesced B fill --------------
// CTA tile: M=128 rows, D = 128 cols interleaved (even=gate j, odd=up j).
// 256 threads = 8 warps (2x4) of 64x32; 2 CTAs/SM.
// B fill: lanes 0-7 cover one full 128B row (1 line), 4 rows/warp-instr = 4 wf.
__global__ void __launch_bounds__(256, 2)
gateup_mma(const float* __restrict__ wgu,
           const float* __restrict__ sgu) {
    int e = blockIdx.z;
    int cnt = g_count[e];
    int m0 = blockIdx.x * 128;
    if (m0 >= cnt) return;
    int n0 = blockIdx.y * 64;
    const float* W = (e < NEXP) ? (wgu + (size_t)e * (2 * IDIM) * HID) : sgu;

    extern __shared__ char smem[];
    uint32_t sb = smem_u32(smem);
    int tid = threadIdx.x;
    int lane = tid & 31, wid = tid >> 5;

    // A cp.async mapping: 512 ops of 16B (128 rows x 4 segs); thread does ops tid, tid+256
    int ar0 = tid >> 2, as0 = tid & 3;
    int ar1 = 64 + ar0;
    int mr0 = m0 + ar0; if (mr0 > cnt - 1) mr0 = cnt - 1;
    int mr1 = m0 + ar1; if (mr1 > cnt - 1) mr1 = cnt - 1;
    const __half* asrc0 = g_xh + (size_t)g_token[e * CAP + mr0] * HID + as0 * 8;
    const __half* asrc1 = g_xh + (size_t)g_token[e * CAP + mr1] * HID + as0 * 8;
    uint32_t adst0 = (uint32_t)(ar0 * STR + as0 * 8) * 2;
    uint32_t adst1 = (uint32_t)(ar1 * STR + as0 * 8) * 2;

    // B loader (coalesced): seg = lane&7 (16B of a 128B row), rows base_r + 4i
    int seg = lane & 7;
    int base_r = wid * 16 + (lane >> 3);         // rows of same parity across i
    int jcol0 = base_r >> 1;
    int wrow0 = (base_r & 1) ? (IDIM + n0 + jcol0) : (n0 + jcol0);
    const float* bptr = W + (size_t)wrow0 * HID + seg * 4;
    uint32_t bdst = TILEB + (uint32_t)(base_r * STR + seg * 4) * 2;
    // gmem row stride per i: +2 weight rows; smem row stride per i: +4 tile rows

    // warp grid 2x4: each warp 64 rows x 32 cols
    int wm0 = (wid >> 2) * 64, wn0 = (wid & 3) * 32;
    uint32_t a_r = (uint32_t)(wm0 + (lane & 15));
    uint32_t a_c8 = (uint32_t)((lane >> 4) * 8);
    uint32_t b_row = (uint32_t)((lane & 7) + ((lane >> 4) << 3));
    uint32_t b_k8 = (uint32_t)(((lane >> 3) & 1) * 8);

    float acc[4][4][4];
    #pragma unroll
    for (int mi = 0; mi < 4; mi++)
        #pragma unroll
        for (int ni = 0; ni < 4; ni++)
            #pragma unroll
            for (int q = 0; q < 4; q++) acc[mi][ni][q] = 0.f;

    float4 rb[4];
    // prologue: chunk 0
    CP_ASYNC16(sb + adst0, asrc0);
    CP_ASYNC16(sb + adst1, asrc1);
    CP_COMMIT();
    #pragma unroll
    for (int q = 0; q < 4; q++) rb[q] = *(const float4*)(bptr + (size_t)q * 2 * HID);
    #pragma unroll
    for (int q = 0; q < 4; q++) store_h(sb + bdst + q * 4 * STR * 2, rb[q]);
    CP_WAIT0();
    __syncthreads();

    const int NC = HID / BK;  // 64
    for (int c = 0; c < NC; c++) {
        if (c + 1 < NC) {
            uint32_t nb = sb + (uint32_t)((c + 1) & 1) * BUFB;
            CP_ASYNC16(nb + adst0, asrc0 + (c + 1) * BK);
            CP_ASYNC16(nb + adst1, asrc1 + (c + 1) * BK);
            CP_COMMIT();
            const float* bp = bptr + (c + 1) * BK;
            #pragma unroll
            for (int q = 0; q < 4; q++) rb[q] = *(const float4*)(bp + (size_t)q * 2 * HID);
        }
        uint32_t cur = sb + (uint32_t)(c & 1) * BUFB;
        #pragma unroll
        for (int kh = 0; kh < 2; kh++) {
            uint32_t ah[4][4], bh[2][4];
            #pragma unroll
            for (int mi = 0; mi < 4; mi++) {
                uint32_t ad = cur + ((a_r + mi * 16) * STR + kh * 16 + a_c8) * 2;
                ldm4(ah[mi], ad);
            }
            #pragma unroll
            for (int nj = 0; nj < 2; nj++) {
                uint32_t bd = cur + TILEB +
                    ((wn0 + nj * 16 + b_row) * STR + kh * 16 + b_k8) * 2;
                ldm4(bh[nj], bd);
            }
            #pragma unroll
            for (int mi = 0; mi < 4; mi++)
                #pragma unroll
                for (int ni = 0; ni < 4; ni++) {
                    const uint32_t* bhp = &bh[ni >> 1][(ni & 1) * 2];
                    mma16816h(acc[mi][ni], ah[mi], bhp);
                }
        }
        if (c + 1 < NC) {
            uint32_t nb = sb + (uint32_t)((c + 1) & 1) * BUFB;
            #pragma unroll
            for (int q = 0; q < 4; q++) store_h(nb + bdst + q * 4 * STR * 2, rb[q]);
        }
        CP_WAIT0();
        __syncthreads();
    }

    // epilogue: c0=gate, c1=up for col j; rows g and g+8 -> fp16 g_act
    int g = lane >> 2, tc = (lane & 3) * 2;
    #pragma unroll
    for (int mi = 0; mi < 4; mi++) {
        int r0 = m0 + wm0 + mi * 16 + g;
        int r1 = r0 + 8;
        #pragma unroll
        for (int ni = 0; ni < 4; ni++) {
            int col = n0 + ((wn0 + ni * 8 + tc) >> 1);
            if (r0 < cnt)
                g_act[((size_t)e * CAP + r0) * IDIM + col] =
                    __float2half_rn(silu_f(acc[mi][ni][0]) * acc[mi][ni][1]);
            if (r1 < cnt)
                g_act[((size_t)e * CAP + r1) * IDIM + col] =
                    __float2half_rn(silu_f(acc[mi][ni][2]) * acc[mi][ni][3]);
        }
    }
}

// ---------------- 4) down GEMM: fp16 mma, coalesced B fill, weighted -------
__global__ void __launch_bounds__(256, 2)
down_mma(const float* __restrict__ wdn,
         const float* __restrict__ sdn) {
    int e = blockIdx.z;
    int cnt = g_count[e];
    int m0 = blockIdx.x * 128;
    if (m0 >= cnt) return;
    int n0 = blockIdx.y * 128;
    const float* W = (e < NEXP) ? (wdn + (size_t)e * HID * IDIM) : sdn;

    extern __shared__ char smem[];
    uint32_t sb = smem_u32(smem);
    int tid = threadIdx.x;
    int lane = tid & 31, wid = tid >> 5;

    int ar0 = tid >> 2, as0 = tid & 3;
    int ar1 = 64 + ar0;
    int mr0 = m0 + ar0; if (mr0 > cnt - 1) mr0 = cnt - 1;
    int mr1 = m0 + ar1; if (mr1 > cnt - 1) mr1 = cnt - 1;
    const __half* asrc0 = g_act + ((size_t)e * CAP + mr0) * IDIM + as0 * 8;
    const __half* asrc1 = g_act + ((size_t)e * CAP + mr1) * IDIM + as0 * 8;
    uint32_t adst0 = (uint32_t)(ar0 * STR + as0 * 8) * 2;
    uint32_t adst1 = (uint32_t)(ar1 * STR + as0 * 8) * 2;

    // B loader (coalesced): seg = lane&7, rows base_r + 4i
    int seg = lane & 7;
    int base_r = wid * 16 + (lane >> 3);
    const float* bptr = W + (size_t)(n0 + base_r) * IDIM + seg * 4;
    uint32_t bdst = TILEB + (uint32_t)(base_r * STR + seg * 4) * 2;

    int wm0 = (wid >> 2) * 64, wn0 = (wid & 3) * 32;
    uint32_t a_r = (uint32_t)(wm0 + (lane & 15));
    uint32_t a_c8 = (uint32_t)((lane >> 4) * 8);
    uint32_t b_row = (uint32_t)((lane & 7) + ((lane >> 4) << 3));
    uint32_t b_k8 = (uint32_t)(((lane >> 3) & 1) * 8);

    float acc[4][4][4];
    #pragma unroll
    for (int mi = 0; mi < 4; mi++)
        #pragma unroll
        for (int ni = 0; ni < 4; ni++)
            #pragma unroll
            for (int q = 0; q < 4; q++) acc[mi][ni][q] = 0.f;

    float4 rb[4];
    CP_ASYNC16(sb + adst0, asrc0);
    CP_ASYNC16(sb + adst1, asrc1);
    CP_COMMIT();
    #pragma unroll
    for (int q = 0; q < 4; q++) rb[q] = *(const float4*)(bptr + (size_t)q * 4 * IDIM);
    #pragma unroll
    for (int q = 0; q < 4; q++) store_h(sb + bdst + q * 4 * STR * 2, rb[q]);
    CP_WAIT0();
    __syncthreads();

    const int NC = IDIM / BK;  // 32
    for (int c = 0; c < NC; c++) {
        if (c + 1 < NC) {
            uint32_t nb = sb + (uint32_t)((c + 1) & 1) * BUFB;
            CP_ASYNC16(nb + adst0, asrc0 + (c + 1) * BK);
            CP_ASYNC16(nb + adst1, asrc1 + (c + 1) * BK);
            CP_COMMIT();
            const float* bp = bptr + (c + 1) * BK;
            #pragma unroll
            for (int q = 0; q < 4; q++) rb[q] = *(const float4*)(bp + (size_t)q * 4 * IDIM);
        }
        uint32_t cur = sb + (uint32_t)(c & 1) * BUFB;
        #pragma unroll
        for (int kh = 0; kh < 2; kh++) {
            uint32_t ah[4][4], bh[2][4];
            #pragma unroll
            for (int mi = 0; mi < 4; mi++) {
                uint32_t ad = cur + ((a_r + mi * 16) * STR + kh * 16 + a_c8) * 2;
                ldm4(ah[mi], ad);
            }
            #pragma unroll
            for (int nj = 0; nj < 2; nj++) {
                uint32_t bd = cur + TILEB +
                    ((wn0 + nj * 16 + b_row) * STR + kh * 16 + b_k8) * 2;
                ldm4(bh[nj], bd);
            }
            #pragma unroll
            for (int mi = 0; mi < 4; mi++)
                #pragma unroll
                for (int ni = 0; ni < 4; ni++) {
                    const uint32_t* bhp = &bh[ni >> 1][(ni & 1) * 2];
                    mma16816h(acc[mi][ni], ah[mi], bhp);
                }
        }
        if (c + 1 < NC) {
            uint32_t nb = sb + (uint32_t)((c + 1) & 1) * BUFB;
            #pragma unroll
            for (int q = 0; q < 4; q++) store_h(nb + bdst + q * 4 * STR * 2, rb[q]);
        }
        CP_WAIT0();
        __syncthreads();
    }

    int g = lane >> 2, tc = (lane & 3) * 2;
    #pragma unroll
    for (int mi = 0; mi < 4; mi++) {
        int r0 = m0 + wm0 + mi * 16 + g;
        int r1 = r0 + 8;
        float w0 = (r0 < cnt) ? g_wt[e * CAP + r0] : 0.f;
        float w1 = (r1 < cnt) ? g_wt[e * CAP + r1] : 0.f;
        #pragma unroll
        for (int ni = 0; ni < 4; ni++) {
            int col = n0 + wn0 + ni * 8 + tc;
            if (r0 < cnt) {
                float2 v = make_float2(acc[mi][ni][0] * w0, acc[mi][ni][1] * w0);
                *(float2*)(g_down + ((size_t)e * CAP + r0) * HID + col) = v;
            }
            if (r1 < cnt) {
                float2 v = make_float2(acc[mi][ni][2] * w1, acc[mi][ni][3] * w1);
                *(float2*)(g_down + ((size_t)e * CAP + r1) * HID + col) = v;
            }
        }
    }
}

// ---------------- 5) deterministic per-token combine ----------------
__global__ void combine_kernel(float* __restrict__ y) {
    int t = blockIdx.x;
    __shared__ int rows[NEXP];
    if (threadIdx.x < NEXP) rows[threadIdx.x] = g_rowid[threadIdx.x * T_TOK + t];
    __syncthreads();
    int h0 = threadIdx.x * 8;
    const float* sh = g_down + ((size_t)NEXP * CAP + t) * HID + h0;
    float4 s0 = *(const float4*)sh;
    float4 s1 = *(const float4*)(sh + 4);
    for (int e = 0; e < NEXP; e++) {
        int r = rows[e];
        if (r >= 0) {
            const float* p = g_down + (size_t)r * HID + h0;
            float4 a = *(const float4*)p;
            float4 b = *(const float4*)(p + 4);
            s0.x += a.x; s0.y += a.y; s0.z += a.z; s0.w += a.w;
            s1.x += b.x; s1.y += b.y; s1.z += b.z; s1.w += b.w;
        }
    }
    float* out = y + (size_t)t * HID + h0;
    *(float4*)out = s0;
    *(float4*)(out + 4) = s1;
}

// ---------------- launcher ----------------
extern "C" void kernel_launch(void* const* d_in, const int* in_sizes, int n_in,
                              void* d_out, int out_size) {
    const float* x    = (const float*)d_in[0];
    const float* gw   = (const float*)d_in[1];
    const float* bias = (const float*)d_in[2];
    const float* wgu  = (const float*)d_in[3];
    const float* wdn  = (const float*)d_in[4];
    const float* sgu  = (const float*)d_in[5];
    const float* sdn  = (const float*)d_in[6];
    float* y = (float*)d_out;

    xcvt_kernel<<<(T_TOK * HID) / (256 * 4), 256>>>(x);
    router_kernel<<<T_TOK, 256>>>(x, gw, bias);
    build_lists_kernel<<<NE, T_TOK>>>();
    dim3 ga(CAP / 128, IDIM / 64, NE);
    gateup_mma<<<ga, 256, SMEMB>>>(wgu, sgu);
    dim3 gd(CAP / 128, HID / 128, NE);
    down_mma<<<gd, 256, SMEMB>>>(wdn, sdn);
    combine_kernel<<<T_TOK, 256>>>(y);
}

// round 16
// speedup vs baseline: 1.6604x; 1.0763x over previous
#include <cuda_runtime.h>
#include <cuda_fp16.h>
#include <cstdint>
#include <cstddef>

#define T_TOK 1024
#define HID   2048
#define IDIM  1024
#define NEXP  32
#define NGRP  8
#define EPG   4
#define TOPG  4
#define TOPK  8
#define NE    33      // 32 routed + 1 shared
#define CAP   1024
#define RSCALE 2.5f

// GEMM tiling: CTA 128x128, 8 warps of 64x32, BK=64, double buffer, cp.async A
#define BK    64
#define STR   72                 // padded fp16 row stride (144B, conflict-free ldmatrix)
#define TILEB (128 * STR * 2)    // 18432 bytes per 128xBK fp16 tile
#define BUFB  (2 * TILEB)        // A + B = 36864
#define SMEMB (2 * BUFB)         // double buffer = 73728

// ---------------- static scratch (no allocations allowed) ----------------
__device__ float  g_combine[T_TOK * NEXP];
__device__ int    g_count[NE];
__device__ int    g_token[NE * CAP];
__device__ float  g_wt[NE * CAP];
__device__ int    g_rowid[NEXP * T_TOK];                    // [e][t] -> row or -1
__device__ __half g_xh[(size_t)T_TOK * HID];                // x in fp16
__device__ __half g_act[(size_t)NE * CAP * IDIM];           // silu(g)*u rows (fp16)
__device__ float  g_down[(size_t)NE * CAP * HID];           // weighted down-proj rows

__device__ __forceinline__ float silu_f(float v) {
    return v / (1.0f + expf(-v));
}

__device__ __forceinline__ uint32_t smem_u32(const void* p) {
    uint32_t a;
    asm("{ .reg .u64 t; cvta.to.shared.u64 t, %1; cvt.u32.u64 %0, t; }"
        : "=r"(a) : "l"(p));
    return a;
}

__device__ __forceinline__ void ldm4(uint32_t* r, uint32_t addr) {
    asm volatile("ldmatrix.sync.aligned.m8n8.x4.shared.b16 {%0,%1,%2,%3}, [%4];"
        : "=r"(r[0]), "=r"(r[1]), "=r"(r[2]), "=r"(r[3]) : "r"(addr));
}
__device__ __forceinline__ void mma16816h(float* c, const uint32_t* a, const uint32_t* b) {
    asm volatile("mma.sync.aligned.m16n8k16.row.col.f32.f16.f16.f32 "
        "{%0,%1,%2,%3}, {%4,%5,%6,%7}, {%8,%9}, {%0,%1,%2,%3};"
        : "+f"(c[0]), "+f"(c[1]), "+f"(c[2]), "+f"(c[3])
        : "r"(a[0]), "r"(a[1]), "r"(a[2]), "r"(a[3]), "r"(b[0]), "r"(b[1]));
}

// fp32x4 -> fp16, store 8B
__device__ __forceinline__ void store_h(uint32_t a, float4 v) {
    __half h0 = __float2half_rn(v.x), h1 = __float2half_rn(v.y);
    __half h2 = __float2half_rn(v.z), h3 = __float2half_rn(v.w);
    unsigned long long H =
        (unsigned long long)__half_as_ushort(h0) |
        ((unsigned long long)__half_as_ushort(h1) << 16) |
        ((unsigned long long)__half_as_ushort(h2) << 32) |
        ((unsigned long long)__half_as_ushort(h3) << 48);
    asm volatile("st.shared.b64 [%0], %1;" :: "r"(a), "l"(H) : "memory");
}

#define CP_ASYNC16(dst, src) \
    asm volatile("cp.async.ca.shared.global [%0], [%1], 16;" :: "r"(dst), "l"(src) : "memory")
#define CP_COMMIT() asm volatile("cp.async.commit_group;" ::: "memory")
#define CP_WAIT0()  asm volatile("cp.async.wait_group 0;" ::: "memory")

// ---------------- 0) x -> fp16 prepass ----------------
__global__ void xcvt_kernel(const float* __restrict__ x) {
    size_t i = ((size_t)blockIdx.x * blockDim.x + threadIdx.x) * 4;
    float4 v = *(const float4*)(x + i);
    __half2* o = (__half2*)(g_xh + i);
    o[0] = __floats2half2_rn(v.x, v.y);
    o[1] = __floats2half2_rn(v.z, v.w);
}

// ---------------- 1) router ----------------
__global__ void router_kernel(const float* __restrict__ x,
                              const float* __restrict__ gw,
                              const float* __restrict__ bias) {
    __shared__ float sx[HID];
    __shared__ float slog[NEXP];
    int t = blockIdx.x;
    const float* xr = x + (size_t)t * HID;
    for (int k = threadIdx.x; k < HID; k += blockDim.x) sx[k] = xr[k];
    __syncthreads();
    int warp = threadIdx.x >> 5, lane = threadIdx.x & 31;
    for (int e = warp; e < NEXP; e += 8) {
        const float* w = gw + (size_t)e * HID;
        float acc = 0.f;
        for (int k = lane; k < HID; k += 32) acc = fmaf(sx[k], w[k], acc);
        #pragma unroll
        for (int o = 16; o; o >>= 1) acc += __shfl_down_sync(0xffffffffu, acc, o);
        if (lane == 0) slog[e] = acc;
    }
    __syncthreads();
    if (threadIdx.x == 0) {
        float s[NEXP], sr[NEXP];
        #pragma unroll
        for (int e = 0; e < NEXP; e++) {
            float sc = 1.f / (1.f + expf(-slog[e]));
            s[e] = sc;
            sr[e] = sc + bias[e];
        }
        float gs[NGRP];
        #pragma unroll
        for (int g = 0; g < NGRP; g++) {
            float m1 = -1e30f, m2 = -1e30f;
            #pragma unroll
            for (int j = 0; j < EPG; j++) {
                float v = sr[g * EPG + j];
                if (v > m1) { m2 = m1; m1 = v; }
                else if (v > m2) { m2 = v; }
            }
            gs[g] = m1 + m2;
        }
        bool gsel[NGRP];
        #pragma unroll
        for (int g = 0; g < NGRP; g++) gsel[g] = false;
        for (int it = 0; it < TOPG; it++) {
            float best = -1e30f; int bi = 0;
            for (int g = 0; g < NGRP; g++)
                if (!gsel[g] && gs[g] > best) { best = gs[g]; bi = g; }
            gsel[bi] = true;
        }
        bool taken[NEXP];
        #pragma unroll
        for (int e = 0; e < NEXP; e++) taken[e] = false;
        int ids[TOPK];
        for (int it = 0; it < TOPK; it++) {
            float best = -1e30f; int bi = 0;
            for (int e = 0; e < NEXP; e++)
                if (gsel[e >> 2] && !taken[e] && sr[e] > best) { best = sr[e]; bi = e; }
            taken[bi] = true;
            ids[it] = bi;
        }
        float sum = 0.f;
        for (int k = 0; k < TOPK; k++) sum += s[ids[k]];
        float inv = RSCALE / (sum + 1e-20f);
        float out[NEXP];
        #pragma unroll
        for (int e = 0; e < NEXP; e++) out[e] = 0.f;
        for (int k = 0; k < TOPK; k++) out[ids[k]] = s[ids[k]] * inv;
        #pragma unroll
        for (int e = 0; e < NEXP; e++) g_combine[t * NEXP + e] = out[e];
    }
}

// ---------------- 2) compact per-expert token lists ----------------
__global__ void build_lists_kernel() {
    int e = blockIdx.x;
    int t = threadIdx.x;
    __shared__ int sc[T_TOK];
    float w;
    int flag;
    if (e < NEXP) {
        w = g_combine[t * NEXP + e];
        flag = (w > 0.f) ? 1 : 0;
    } else {
        w = 1.0f;
        flag = 1;
    }
    sc[t] = flag;
    __syncthreads();
    for (int off = 1; off < T_TOK; off <<= 1) {
        int v = (t >= off) ? sc[t - off] : 0;
        __syncthreads();
        sc[t] += v;
        __syncthreads();
    }
    int pos = sc[t] - flag;
    if (flag) {
        g_token[e * CAP + pos] = t;
        g_wt[e * CAP + pos] = w;
    }
    if (e < NEXP) g_rowid[e * T_TOK + t] = flag ? (e * CAP + pos) : -1;
    if (t == T_TOK - 1) g_count[e] = sc[T_TOK - 1];
}

// ---------------- 3) gate_up GEMM: fp16 mma, BK=64, coalesced B ------------
// CTA tile: M=128 rows, D = 128 cols interleaved (even=gate j, odd=up j).
// 256 threads = 8 warps (2x4) of 64x32; 2 CTAs/SM.
__global__ void __launch_bounds__(256, 2)
gateup_mma(const float* __restrict__ wgu,
           const float* __restrict__ sgu) {
    int e = blockIdx.z;
    int cnt = g_count[e];
    int m0 = blockIdx.x * 128;
    if (m0 >= cnt) return;
    int n0 = blockIdx.y * 64;
    const float* W = (e < NEXP) ? (wgu + (size_t)e * (2 * IDIM) * HID) : sgu;

    extern __shared__ char smem[];
    uint32_t sb = smem_u32(smem);
    int tid = threadIdx.x;
    int lane = tid & 31, wid = tid >> 5;

    // A cp.async: 1024 x 16B ops (128 rows x 8 segs); thread does 4 ops
    int arow = tid >> 3, aseg = tid & 7;
    const __half* asrc[4];
    uint32_t adst[4];
    #pragma unroll
    for (int i = 0; i < 4; i++) {
        int row = arow + 32 * i;
        int mr = m0 + row; if (mr > cnt - 1) mr = cnt - 1;
        asrc[i] = g_xh + (size_t)g_token[e * CAP + mr] * HID + aseg * 8;
        adst[i] = (uint32_t)(row * STR + aseg * 8) * 2;
    }

    // B loader (coalesced): lane = (h, seg16); rows r = wid*16 + h + 2i
    int h = lane >> 4, seg16 = lane & 15;
    int wbase = (h ? (IDIM + n0 + wid * 8) : (n0 + wid * 8));
    const float* bptr = W + (size_t)wbase * HID + seg16 * 4;
    uint32_t bdst = TILEB + (uint32_t)((wid * 16 + h) * STR + seg16 * 4) * 2;
    // per i: gmem += HID floats, smem += 2*STR*2 bytes

    // warp grid 2x4: each warp 64 rows x 32 cols
    int wm0 = (wid >> 2) * 64, wn0 = (wid & 3) * 32;
    uint32_t a_r = (uint32_t)(wm0 + (lane & 15));
    uint32_t a_c8 = (uint32_t)((lane >> 4) * 8);
    uint32_t b_row = (uint32_t)((lane & 7) + ((lane >> 4) << 3));
    uint32_t b_k8 = (uint32_t)(((lane >> 3) & 1) * 8);

    float acc[4][4][4];
    #pragma unroll
    for (int mi = 0; mi < 4; mi++)
        #pragma unroll
        for (int ni = 0; ni < 4; ni++)
            #pragma unroll
            for (int q = 0; q < 4; q++) acc[mi][ni][q] = 0.f;

    float4 rb[8];
    // prologue: chunk 0
    #pragma unroll
    for (int i = 0; i < 4; i++) CP_ASYNC16(sb + adst[i], asrc[i]);
    CP_COMMIT();
    #pragma unroll
    for (int i = 0; i < 8; i++) rb[i] = *(const float4*)(bptr + (size_t)i * HID);
    #pragma unroll
    for (int i = 0; i < 8; i++) store_h(sb + bdst + i * (2 * STR * 2), rb[i]);
    CP_WAIT0();
    __syncthreads();

    const int NC = HID / BK;  // 32
    for (int c = 0; c < NC; c++) {
        if (c + 1 < NC) {
            uint32_t nb = sb + (uint32_t)((c + 1) & 1) * BUFB;
            #pragma unroll
            for (int i = 0; i < 4; i++)
                CP_ASYNC16(nb + adst[i], asrc[i] + (c + 1) * BK);
            CP_COMMIT();
            const float* bp = bptr + (c + 1) * BK;
            #pragma unroll
            for (int i = 0; i < 8; i++) rb[i] = *(const float4*)(bp + (size_t)i * HID);
        }
        uint32_t cur = sb + (uint32_t)(c & 1) * BUFB;
        #pragma unroll
        for (int kh = 0; kh < 4; kh++) {
            uint32_t ah[4][4], bh[2][4];
            #pragma unroll
            for (int mi = 0; mi < 4; mi++) {
                uint32_t ad = cur + ((a_r + mi * 16) * STR + kh * 16 + a_c8) * 2;
                ldm4(ah[mi], ad);
            }
            #pragma unroll
            for (int nj = 0; nj < 2; nj++) {
                uint32_t bd = cur + TILEB +
                    ((wn0 + nj * 16 + b_row) * STR + kh * 16 + b_k8) * 2;
                ldm4(bh[nj], bd);
            }
            #pragma unroll
            for (int mi = 0; mi < 4; mi++)
                #pragma unroll
                for (int ni = 0; ni < 4; ni++) {
                    const uint32_t* bhp = &bh[ni >> 1][(ni & 1) * 2];
                    mma16816h(acc[mi][ni], ah[mi], bhp);
                }
        }
        if (c + 1 < NC) {
            uint32_t nb = sb + (uint32_t)((c + 1) & 1) * BUFB;
            #pragma unroll
            for (int i = 0; i < 8; i++) store_h(nb + bdst + i * (2 * STR * 2), rb[i]);
        }
        CP_WAIT0();
        __syncthreads();
    }

    // epilogue: c0=gate, c1=up for col j; rows g and g+8 -> fp16 g_act
    int g = lane >> 2, tc = (lane & 3) * 2;
    #pragma unroll
    for (int mi = 0; mi < 4; mi++) {
        int r0 = m0 + wm0 + mi * 16 + g;
        int r1 = r0 + 8;
        #pragma unroll
        for (int ni = 0; ni < 4; ni++) {
            int col = n0 + ((wn0 + ni * 8 + tc) >> 1);
            if (r0 < cnt)
                g_act[((size_t)e * CAP + r0) * IDIM + col] =
                    __float2half_rn(silu_f(acc[mi][ni][0]) * acc[mi][ni][1]);
            if (r1 < cnt)
                g_act[((size_t)e * CAP + r1) * IDIM + col] =
                    __float2half_rn(silu_f(acc[mi][ni][2]) * acc[mi][ni][3]);
        }
    }
}

// ---------------- 4) down GEMM: fp16 mma, BK=64, coalesced B, weighted -----
__global__ void __launch_bounds__(256, 2)
down_mma(const float* __restrict__ wdn,
         const float* __restrict__ sdn) {
    int e = blockIdx.z;
    int cnt = g_count[e];
    int m0 = blockIdx.x * 128;
    if (m0 >= cnt) return;
    int n0 = blockIdx.y * 128;
    const float* W = (e < NEXP) ? (wdn + (size_t)e * HID * IDIM) : sdn;

    extern __shared__ char smem[];
    uint32_t sb = smem_u32(smem);
    int tid = threadIdx.x;
    int lane = tid & 31, wid = tid >> 5;

    int arow = tid >> 3, aseg = tid & 7;
    const __half* asrc[4];
    uint32_t adst[4];
    #pragma unroll
    for (int i = 0; i < 4; i++) {
        int row = arow + 32 * i;
        int mr = m0 + row; if (mr > cnt - 1) mr = cnt - 1;
        asrc[i] = g_act + ((size_t)e * CAP + mr) * IDIM + aseg * 8;
        adst[i] = (uint32_t)(row * STR + aseg * 8) * 2;
    }

    // B loader (coalesced): rows r = wid*16 + h + 2i -> wrow = n0 + r
    int h = lane >> 4, seg16 = lane & 15;
    const float* bptr = W + (size_t)(n0 + wid * 16 + h) * IDIM + seg16 * 4;
    uint32_t bdst = TILEB + (uint32_t)((wid * 16 + h) * STR + seg16 * 4) * 2;
    // per i: gmem += 2*IDIM floats, smem += 2*STR*2 bytes

    int wm0 = (wid >> 2) * 64, wn0 = (wid & 3) * 32;
    uint32_t a_r = (uint32_t)(wm0 + (lane & 15));
    uint32_t a_c8 = (uint32_t)((lane >> 4) * 8);
    uint32_t b_row = (uint32_t)((lane & 7) + ((lane >> 4) << 3));
    uint32_t b_k8 = (uint32_t)(((lane >> 3) & 1) * 8);

    float acc[4][4][4];
    #pragma unroll
    for (int mi = 0; mi < 4; mi++)
        #pragma unroll
        for (int ni = 0; ni < 4; ni++)
            #pragma unroll
            for (int q = 0; q < 4; q++) acc[mi][ni][q] = 0.f;

    float4 rb[8];
    #pragma unroll
    for (int i = 0; i < 4; i++) CP_ASYNC16(sb + adst[i], asrc[i]);
    CP_COMMIT();
    #pragma unroll
    for (int i = 0; i < 8; i++) rb[i] = *(const float4*)(bptr + (size_t)i * 2 * IDIM);
    #pragma unroll
    for (int i = 0; i < 8; i++) store_h(sb + bdst + i * (2 * STR * 2), rb[i]);
    CP_WAIT0();
    __syncthreads();

    const int NC = IDIM / BK;  // 16
    for (int c = 0; c < NC; c++) {
        if (c + 1 < NC) {
            uint32_t nb = sb + (uint32_t)((c + 1) & 1) * BUFB;
            #pragma unroll
            for (int i = 0; i < 4; i++)
                CP_ASYNC16(nb + adst[i], asrc[i] + (c + 1) * BK);
            CP_COMMIT();
            const float* bp = bptr + (c + 1) * BK;
            #pragma unroll
            for (int i = 0; i < 8; i++) rb[i] = *(const float4*)(bp + (size_t)i * 2 * IDIM);
        }
        uint32_t cur = sb + (uint32_t)(c & 1) * BUFB;
        #pragma unroll
        for (int kh = 0; kh < 4; kh++) {
            uint32_t ah[4][4], bh[2][4];
            #pragma unroll
            for (int mi = 0; mi < 4; mi++) {
                uint32_t ad = cur + ((a_r + mi * 16) * STR + kh * 16 + a_c8) * 2;
                ldm4(ah[mi], ad);
            }
            #pragma unroll
            for (int nj = 0; nj < 2; nj++) {
                uint32_t bd = cur + TILEB +
                    ((wn0 + nj * 16 + b_row) * STR + kh * 16 + b_k8) * 2;
                ldm4(bh[nj], bd);
            }
            #pragma unroll
            for (int mi = 0; mi < 4; mi++)
                #pragma unroll
                for (int ni = 0; ni < 4; ni++) {
                    const uint32_t* bhp = &bh[ni >> 1][(ni & 1) * 2];
                    mma16816h(acc[mi][ni], ah[mi], bhp);
                }
        }
        if (c + 1 < NC) {
            uint32_t nb = sb + (uint32_t)((c + 1) & 1) * BUFB;
            #pragma unroll
            for (int i = 0; i < 8; i++) store_h(nb + bdst + i * (2 * STR * 2), rb[i]);
        }
        CP_WAIT0();
        __syncthreads();
    }

    int g = lane >> 2, tc = (lane & 3) * 2;
    #pragma unroll
    for (int mi = 0; mi < 4; mi++) {
        int r0 = m0 + wm0 + mi * 16 + g;
        int r1 = r0 + 8;
        float w0 = (r0 < cnt) ? g_wt[e * CAP + r0] : 0.f;
        float w1 = (r1 < cnt) ? g_wt[e * CAP + r1] : 0.f;
        #pragma unroll
        for (int ni = 0; ni < 4; ni++) {
            int col = n0 + wn0 + ni * 8 + tc;
            if (r0 < cnt) {
                float2 v = make_float2(acc[mi][ni][0] * w0, acc[mi][ni][1] * w0);
                *(float2*)(g_down + ((size_t)e * CAP + r0) * HID + col) = v;
            }
            if (r1 < cnt) {
                float2 v = make_float2(acc[mi][ni][2] * w1, acc[mi][ni][3] * w1);
                *(float2*)(g_down + ((size_t)e * CAP + r1) * HID + col) = v;
            }
        }
    }
}

// ---------------- 5) deterministic per-token combine ----------------
__global__ void combine_kernel(float* __restrict__ y) {
    int t = blockIdx.x;
    __shared__ int rows[NEXP];
    if (threadIdx.x < NEXP) rows[threadIdx.x] = g_rowid[threadIdx.x * T_TOK + t];
    __syncthreads();
    int h0 = threadIdx.x * 8;
    const float* sh = g_down + ((size_t)NEXP * CAP + t) * HID + h0;
    float4 s0 = *(const float4*)sh;
    float4 s1 = *(const float4*)(sh + 4);
    for (int e = 0; e < NEXP; e++) {
        int r = rows[e];
        if (r >= 0) {
            const float* p = g_down + (size_t)r * HID + h0;
            float4 a = *(const float4*)p;
            float4 b = *(const float4*)(p + 4);
            s0.x += a.x; s0.y += a.y; s0.z += a.z; s0.w += a.w;
            s1.x += b.x; s1.y += b.y; s1.z += b.z; s1.w += b.w;
        }
    }
    float* out = y + (size_t)t * HID + h0;
    *(float4*)out = s0;
    *(float4*)(out + 4) = s1;
}

// ---------------- launcher ----------------
extern "C" void kernel_launch(void* const* d_in, const int* in_sizes, int n_in,
                              void* d_out, int out_size) {
    const float* x    = (const float*)d_in[0];
    const float* gw   = (const float*)d_in[1];
    const float* bias = (const float*)d_in[2];
    const float* wgu  = (const float*)d_in[3];
    const float* wdn  = (const float*)d_in[4];
    const float* sgu  = (const float*)d_in[5];
    const float* sdn  = (const float*)d_in[6];
    float* y = (float*)d_out;

    cudaFuncSetAttribute(gateup_mma, cudaFuncAttributeMaxDynamicSharedMemorySize, SMEMB);
    cudaFuncSetAttribute(down_mma, cudaFuncAttributeMaxDynamicSharedMemorySize, SMEMB);

    xcvt_kernel<<<(T_TOK * HID) / (256 * 4), 256>>>(x);
    router_kernel<<<T_TOK, 256>>>(x, gw, bias);
    build_lists_kernel<<<NE, T_TOK>>>();
    dim3 ga(CAP / 128, IDIM / 64, NE);
    gateup_mma<<<ga, 256, SMEMB>>>(wgu, sgu);
    dim3 gd(CAP / 128, HID / 128, NE);
    down_mma<<<gd, 256, SMEMB>>>(wdn, sdn);
    combine_kernel<<<T_TOK, 256>>>(y);
}